// round 2
// baseline (speedup 1.0000x reference)
#include <cuda_runtime.h>
#include <cuda_bf16.h>

// Problem shape (fixed by the reference):
//   query: (N,T,C,L) = (32,64,256,64) fp32, row-major, L innermost
//   key:   (T,N,C)   = (64,32,256)    fp32
//   out:   (T,N,C)   = (64,32,256)    fp32
#define N_ 32
#define T_ 64
#define C_ 256
#define L_ 64

// Scratch (no cudaMalloc allowed): per-(n,t) partial scores + softmax probs.
__device__ float g_part[N_ * T_ * L_];   // [(n*T+t)][l]
__device__ float g_probs[N_ * L_];       // [n][l]

// ---------------------------------------------------------------------------
// Kernel 1: partial scores. One block per (n,t). 8 warps; each warp handles 32
// consecutive c-rows. Lane holds an l-pair (float2) -> each warp LDG.64 reads
// one full 256B row, fully coalesced. Block-reduce across warps into g_part.
// ---------------------------------------------------------------------------
__global__ __launch_bounds__(256) void k_scores(const float* __restrict__ q,
                                                const float* __restrict__ key) {
    const int b = blockIdx.x;          // b = n*T_ + t
    const int n = b >> 6;
    const int t = b & 63;
    const int w = threadIdx.x >> 5;
    const int lane = threadIdx.x & 31;

    const float2* __restrict__ qb = reinterpret_cast<const float2*>(q);
    const size_t rowbase = (size_t)b * C_;                 // row index base (rows of 64 floats)
    const float* __restrict__ kp = key + ((size_t)t * N_ + n) * C_;

    float2 acc = make_float2(0.f, 0.f);
    #pragma unroll 8
    for (int i = 0; i < 32; ++i) {
        const int c = (w << 5) + i;
        const float kv = __ldg(kp + c);                    // uniform per warp
        const float2 qv = qb[(rowbase + c) * 32 + lane];   // coalesced 256B/warp
        acc.x = fmaf(kv, qv.x, acc.x);
        acc.y = fmaf(kv, qv.y, acc.y);
    }

    __shared__ float2 sm[8][32];
    sm[w][lane] = acc;
    __syncthreads();
    if (w == 0) {
        float2 tot = sm[0][lane];
        #pragma unroll
        for (int j = 1; j < 8; ++j) {
            tot.x += sm[j][lane].x;
            tot.y += sm[j][lane].y;
        }
        float* dst = g_part + (size_t)b * L_;
        dst[2 * lane]     = tot.x;
        dst[2 * lane + 1] = tot.y;
    }
}

// ---------------------------------------------------------------------------
// Kernel 2: reduce partials over t, then stable softmax over l for each n.
// 32 blocks x 64 threads (2 warps). Tiny: ~512KB read total.
// ---------------------------------------------------------------------------
__global__ __launch_bounds__(64) void k_softmax() {
    const int n = blockIdx.x;
    const int l = threadIdx.x;

    float s = 0.f;
    const float* __restrict__ p = g_part + (size_t)n * T_ * L_ + l;
    #pragma unroll
    for (int t = 0; t < T_; ++t) s += p[(size_t)t * L_];   // coalesced over l

    // max across 64 threads (2 warps)
    float m = s;
    #pragma unroll
    for (int off = 16; off; off >>= 1)
        m = fmaxf(m, __shfl_xor_sync(0xffffffffu, m, off));
    __shared__ float wm[2];
    if ((l & 31) == 0) wm[l >> 5] = m;
    __syncthreads();
    m = fmaxf(wm[0], wm[1]);

    const float e = __expf(s - m);
    float sum = e;
    #pragma unroll
    for (int off = 16; off; off >>= 1)
        sum += __shfl_xor_sync(0xffffffffu, sum, off);
    __shared__ float ws[2];
    if ((l & 31) == 0) ws[l >> 5] = sum;
    __syncthreads();
    sum = ws[0] + ws[1];

    g_probs[n * L_ + l] = e / sum;
}

// ---------------------------------------------------------------------------
// Kernel 3: out[t,n,c] = sum_l q[n,t,c,l] * probs[n,l].
// Same (n,t)-block / warp-per-row structure as kernel 1; 5-level shfl reduce
// per row; lane 0 writes the scalar.
// ---------------------------------------------------------------------------
__global__ __launch_bounds__(256) void k_out(const float* __restrict__ q,
                                             float* __restrict__ out) {
    const int b = blockIdx.x;
    const int n = b >> 6;
    const int t = b & 63;
    const int w = threadIdx.x >> 5;
    const int lane = threadIdx.x & 31;

    const float2 pp = reinterpret_cast<const float2*>(g_probs + n * L_)[lane];
    const float2* __restrict__ qb = reinterpret_cast<const float2*>(q);
    const size_t rowbase = (size_t)b * C_;
    float* __restrict__ ob = out + ((size_t)t * N_ + n) * C_;

    #pragma unroll 4
    for (int i = 0; i < 32; ++i) {
        const int c = (w << 5) + i;
        const float2 qv = qb[(rowbase + c) * 32 + lane];
        float v = fmaf(qv.x, pp.x, qv.y * pp.y);
        #pragma unroll
        for (int off = 16; off; off >>= 1)
            v += __shfl_xor_sync(0xffffffffu, v, off);
        if (lane == 0) ob[c] = v;
    }
}

extern "C" void kernel_launch(void* const* d_in, const int* in_sizes, int n_in,
                              void* d_out, int out_size) {
    const float* q   = (const float*)d_in[0];   // (32,64,256,64)
    const float* key = (const float*)d_in[1];   // (64,32,256)
    float* out = (float*)d_out;                 // (64,32,256)

    k_scores<<<N_ * T_, 256>>>(q, key);
    k_softmax<<<N_, 64>>>();
    k_out<<<N_ * T_, 256>>>(q, out);
}

// round 3
// speedup vs baseline: 1.2533x; 1.2533x over previous
#include <cuda_runtime.h>
#include <cuda_bf16.h>

// Shapes: query (N,T,C,L)=(32,64,256,64) fp32; key (T,N,C); out (T,N,C)
#define N_ 32
#define T_ 64
#define C_ 256
#define L_ 64

__device__ float g_part[N_ * T_ * L_];   // per-(n,t) partial scores
__device__ float g_probs[N_ * L_];       // softmax probs per n

// ---------------------------------------------------------------------------
// Kernel 1: partial scores. One block per (n,t)=b. 8 warps; each warp covers
// 32 c-rows, processing 2 rows/iter: half-warp per row, lane holds an
// l-quad (float4 -> LDG.128, 512B per warp per load, fully coalesced).
// ---------------------------------------------------------------------------
__global__ __launch_bounds__(256) void k_scores(const float* __restrict__ q,
                                                const float* __restrict__ key) {
    const int b = blockIdx.x;          // b = n*T_ + t
    const int n = b >> 6;
    const int t = b & 63;
    const int w = threadIdx.x >> 5;
    const int lane = threadIdx.x & 31;
    const int half = lane >> 4;        // which row of the pair
    const int l4 = lane & 15;          // float4 index within the 64-float row

    const float4* __restrict__ qb = reinterpret_cast<const float4*>(q);
    const size_t rowbase = (size_t)b * C_;   // row index (rows of 64 floats = 16 float4)
    const float* __restrict__ kp = key + ((size_t)t * N_ + n) * C_;

    float4 acc = make_float4(0.f, 0.f, 0.f, 0.f);
    #pragma unroll 8
    for (int i = 0; i < 16; ++i) {
        const int c = (w << 5) + (i << 1) + half;
        const float kv = __ldg(kp + c);
        const float4 qv = qb[(rowbase + c) * 16 + l4];
        acc.x = fmaf(kv, qv.x, acc.x);
        acc.y = fmaf(kv, qv.y, acc.y);
        acc.z = fmaf(kv, qv.z, acc.z);
        acc.w = fmaf(kv, qv.w, acc.w);
    }

    // combine the two halves of the warp (same l4, different rows)
    acc.x += __shfl_xor_sync(0xffffffffu, acc.x, 16);
    acc.y += __shfl_xor_sync(0xffffffffu, acc.y, 16);
    acc.z += __shfl_xor_sync(0xffffffffu, acc.z, 16);
    acc.w += __shfl_xor_sync(0xffffffffu, acc.w, 16);

    __shared__ float4 sm[8][16];
    if (half == 0) sm[w][l4] = acc;
    __syncthreads();

    if (threadIdx.x < 16) {
        float4 tot = sm[0][threadIdx.x];
        #pragma unroll
        for (int j = 1; j < 8; ++j) {
            const float4 v = sm[j][threadIdx.x];
            tot.x += v.x; tot.y += v.y; tot.z += v.z; tot.w += v.w;
        }
        reinterpret_cast<float4*>(g_part + (size_t)b * L_)[threadIdx.x] = tot;
    }
}

// ---------------------------------------------------------------------------
// Kernel 2: reduce partials over t, stable softmax over l. 32 blocks x 64 thr.
// ---------------------------------------------------------------------------
__global__ __launch_bounds__(64) void k_softmax() {
    const int n = blockIdx.x;
    const int l = threadIdx.x;

    float s = 0.f;
    const float* __restrict__ p = g_part + (size_t)n * T_ * L_ + l;
    #pragma unroll
    for (int t = 0; t < T_; ++t) s += p[(size_t)t * L_];

    float m = s;
    #pragma unroll
    for (int off = 16; off; off >>= 1)
        m = fmaxf(m, __shfl_xor_sync(0xffffffffu, m, off));
    __shared__ float wm[2];
    if ((l & 31) == 0) wm[l >> 5] = m;
    __syncthreads();
    m = fmaxf(wm[0], wm[1]);

    const float e = __expf(s - m);
    float sum = e;
    #pragma unroll
    for (int off = 16; off; off >>= 1)
        sum += __shfl_xor_sync(0xffffffffu, sum, off);
    __shared__ float ws[2];
    if ((l & 31) == 0) ws[l >> 5] = sum;
    __syncthreads();
    sum = ws[0] + ws[1];

    g_probs[n * L_ + l] = e / sum;
}

// ---------------------------------------------------------------------------
// Kernel 3: out[t,n,c] = sum_l q[n,t,c,l] * probs[n,l].
// REVERSED block mapping: k_scores streamed q front-to-back, so the TAIL of q
// is still L2-resident (L2 ~126MB vs q 128MB). Read tail-first to hit it.
// float4 loads, half-warp per row, 4-level shfl reduce within the half-warp.
// ---------------------------------------------------------------------------
__global__ __launch_bounds__(256) void k_out(const float* __restrict__ q,
                                             float* __restrict__ out) {
    const int b = (N_ * T_ - 1) - blockIdx.x;   // reverse order for L2 reuse
    const int n = b >> 6;
    const int t = b & 63;
    const int w = threadIdx.x >> 5;
    const int lane = threadIdx.x & 31;
    const int half = lane >> 4;
    const int l4 = lane & 15;

    const float4 pv = reinterpret_cast<const float4*>(g_probs + n * L_)[l4];
    const float4* __restrict__ qb = reinterpret_cast<const float4*>(q);
    const size_t rowbase = (size_t)b * C_;
    float* __restrict__ ob = out + ((size_t)t * N_ + n) * C_;

    #pragma unroll 8
    for (int i = 0; i < 16; ++i) {
        const int c = (w << 5) + (i << 1) + half;
        const float4 qv = qb[(rowbase + c) * 16 + l4];
        float v = fmaf(qv.x, pv.x, fmaf(qv.y, pv.y, fmaf(qv.z, pv.z, qv.w * pv.w)));
        #pragma unroll
        for (int off = 8; off; off >>= 1)
            v += __shfl_xor_sync(0xffffffffu, v, off);
        if (l4 == 0) ob[c] = v;
    }
}

extern "C" void kernel_launch(void* const* d_in, const int* in_sizes, int n_in,
                              void* d_out, int out_size) {
    const float* q   = (const float*)d_in[0];
    const float* key = (const float*)d_in[1];
    float* out = (float*)d_out;

    k_scores<<<N_ * T_, 256>>>(q, key);
    k_softmax<<<N_, 64>>>();
    k_out<<<N_ * T_, 256>>>(q, out);
}

// round 4
// speedup vs baseline: 1.3673x; 1.0910x over previous
#include <cuda_runtime.h>
#include <cuda_bf16.h>

// Shapes: query (N,T,C,L)=(32,64,256,64) fp32; key (T,N,C); out (T,N,C)
#define N_ 32
#define T_ 64
#define C_ 256
#define L_ 64

__device__ float g_part[N_ * T_ * L_];   // per-(n,t) partial scores
__device__ float g_probs[N_ * L_];       // softmax probs per n

// ---------------------------------------------------------------------------
// Kernel 1: partial scores. One block per (n,t)=b. 8 warps; each warp covers
// 32 consecutive c-rows. Lane holds an l-pair (float2 -> LDG.64, 256B/warp,
// fully coalesced). Key row is preloaded into registers (one value per lane)
// and broadcast with shfl -> zero memory ops in the loop besides the q stream.
// ---------------------------------------------------------------------------
__global__ __launch_bounds__(256) void k_scores(const float* __restrict__ q,
                                                const float* __restrict__ key) {
    const int b = blockIdx.x;          // b = n*T_ + t
    const int n = b >> 6;
    const int t = b & 63;
    const int w = threadIdx.x >> 5;
    const int lane = threadIdx.x & 31;

    // Preload this warp's 32 key values: one per lane (coalesced 128B LDG).
    const float kreg = key[((size_t)t * N_ + n) * C_ + (w << 5) + lane];

    const float2* __restrict__ qb = reinterpret_cast<const float2*>(q);
    const size_t rowbase = (size_t)b * C_;   // row index (rows of 32 float2)

    float2 acc = make_float2(0.f, 0.f);
    #pragma unroll 8
    for (int i = 0; i < 32; ++i) {
        const float kv = __shfl_sync(0xffffffffu, kreg, i);
        const float2 qv = qb[(rowbase + (w << 5) + i) * 32 + lane];
        acc.x = fmaf(kv, qv.x, acc.x);
        acc.y = fmaf(kv, qv.y, acc.y);
    }

    __shared__ float2 sm[8][32];
    sm[w][lane] = acc;
    __syncthreads();
    if (w == 0) {
        float2 tot = sm[0][lane];
        #pragma unroll
        for (int j = 1; j < 8; ++j) {
            tot.x += sm[j][lane].x;
            tot.y += sm[j][lane].y;
        }
        reinterpret_cast<float2*>(g_part + (size_t)b * L_)[lane] = tot;
    }
}

// ---------------------------------------------------------------------------
// Kernel 2: reduce partials over t, stable softmax over l. 32 blocks x 64 thr.
// ---------------------------------------------------------------------------
__global__ __launch_bounds__(64) void k_softmax() {
    const int n = blockIdx.x;
    const int l = threadIdx.x;

    float s = 0.f;
    const float* __restrict__ p = g_part + (size_t)n * T_ * L_ + l;
    #pragma unroll
    for (int t = 0; t < T_; ++t) s += p[(size_t)t * L_];

    float m = s;
    #pragma unroll
    for (int off = 16; off; off >>= 1)
        m = fmaxf(m, __shfl_xor_sync(0xffffffffu, m, off));
    __shared__ float wm[2];
    if ((l & 31) == 0) wm[l >> 5] = m;
    __syncthreads();
    m = fmaxf(wm[0], wm[1]);

    const float e = __expf(s - m);
    float sum = e;
    #pragma unroll
    for (int off = 16; off; off >>= 1)
        sum += __shfl_xor_sync(0xffffffffu, sum, off);
    __shared__ float ws[2];
    if ((l & 31) == 0) ws[l >> 5] = sum;
    __syncthreads();
    sum = ws[0] + ws[1];

    g_probs[n * L_ + l] = e / sum;
}

// ---------------------------------------------------------------------------
// Kernel 3: out[t,n,c] = sum_l q[n,t,c,l] * probs[n,l].
// REVERSED block mapping: k_scores streamed q front-to-back, so the TAIL of q
// is still L2-resident (L2 ~126MB vs q 128MB). Read tail-first to hit it.
// float4 loads, half-warp per row, 4-level shfl reduce within the half-warp.
// (Unchanged from R2 — measured near the L2-bandwidth floor.)
// ---------------------------------------------------------------------------
__global__ __launch_bounds__(256) void k_out(const float* __restrict__ q,
                                             float* __restrict__ out) {
    const int b = (N_ * T_ - 1) - blockIdx.x;   // reverse order for L2 reuse
    const int n = b >> 6;
    const int t = b & 63;
    const int w = threadIdx.x >> 5;
    const int lane = threadIdx.x & 31;
    const int half = lane >> 4;
    const int l4 = lane & 15;

    const float4 pv = reinterpret_cast<const float4*>(g_probs + n * L_)[l4];
    const float4* __restrict__ qb = reinterpret_cast<const float4*>(q);
    const size_t rowbase = (size_t)b * C_;
    float* __restrict__ ob = out + ((size_t)t * N_ + n) * C_;

    #pragma unroll 8
    for (int i = 0; i < 16; ++i) {
        const int c = (w << 5) + (i << 1) + half;
        const float4 qv = qb[(rowbase + c) * 16 + l4];
        float v = fmaf(qv.x, pv.x, fmaf(qv.y, pv.y, fmaf(qv.z, pv.z, qv.w * pv.w)));
        #pragma unroll
        for (int off = 8; off; off >>= 1)
            v += __shfl_xor_sync(0xffffffffu, v, off);
        if (l4 == 0) ob[c] = v;
    }
}

extern "C" void kernel_launch(void* const* d_in, const int* in_sizes, int n_in,
                              void* d_out, int out_size) {
    const float* q   = (const float*)d_in[0];
    const float* key = (const float*)d_in[1];
    float* out = (float*)d_out;

    k_scores<<<N_ * T_, 256>>>(q, key);
    k_softmax<<<N_, 64>>>();
    k_out<<<N_ * T_, 256>>>(q, out);
}